// round 1
// baseline (speedup 1.0000x reference)
#include <cuda_runtime.h>

// Problem dims
#define B_ 32
#define P_ 12
#define N_ 512
#define F_ 64
#define D_ 256
#define Q_ 12
#define DT_ 0.1f

static const int BQN = B_ * Q_ * N_;  // 196608

// ---------------- scratch (device globals; no runtime alloc) ----------------
__device__ float g_tmp[(size_t)B_ * Q_ * N_ * F_];   // mixed inputs  (B,Q,N,F)
__device__ float g_h  [(size_t)B_ * Q_ * N_ * D_];   // hidden        (B,Q,N,D)
__device__ float g_q  [(size_t)B_ * Q_ * N_ * D_];
__device__ float g_k  [(size_t)B_ * Q_ * N_ * D_];
__device__ float g_v  [(size_t)B_ * Q_ * N_ * D_];
__device__ float g_S  [(size_t)B_ * Q_ * N_ * N_];   // scores/attn   (B,Q,N,N)
__device__ float g_Fm [(size_t)N_ * N_];             // I + DT*A

// ---------------- K1: tmp[b,q,n,f] = sum_p inputs[b,p,n,f] * T_mix[p,q] -----
// (apply the 12x12 time-mix BEFORE the F->D projection: 4x cheaper than ref order)
__global__ __launch_bounds__(256) void mix_kernel(const float* __restrict__ in,
                                                  const float* __restrict__ T) {
    __shared__ float Ts[P_][Q_];
    int t = threadIdx.x;
    if (t < P_ * Q_) Ts[t / Q_][t % Q_] = T[t];
    __syncthreads();
    long idx = (long)blockIdx.x * blockDim.x + t;          // over B*N*F
    if (idx >= (long)B_ * N_ * F_) return;
    int f = (int)(idx % F_);
    int n = (int)((idx / F_) % N_);
    int b = (int)(idx / ((long)F_ * N_));
    float vals[P_];
    const float* ip = in + ((long)b * P_ * N_ + n) * F_ + f;
#pragma unroll
    for (int p = 0; p < P_; p++) vals[p] = ip[(long)p * N_ * F_];
    float* op = g_tmp + ((long)b * Q_ * N_ + n) * F_ + f;
#pragma unroll
    for (int q = 0; q < Q_; q++) {
        float s = 0.f;
#pragma unroll
        for (int p = 0; p < P_; p++) s += vals[p] * Ts[p][q];
        op[(long)q * N_ * F_] = s;
    }
}

// ---------------- Fm = I + DT*A ---------------------------------------------
__global__ __launch_bounds__(256) void fm_kernel(const float* __restrict__ A) {
    int i = blockIdx.x * blockDim.x + threadIdx.x;
    if (i < N_ * N_) {
        int n = i / N_, m = i % N_;
        g_Fm[i] = DT_ * A[i] + ((n == m) ? 1.f : 0.f);
    }
}

// ---------------- generic tiled SGEMM (64x64x16, 256 thr, 4x4 micro) --------
// C = alpha * A * op(B) (+ R).  A: MxK row-major.  NN: B is KxN row-major.
// NT: B is NxK row-major (C = A*B^T).  Batched via blockIdx.z with strides.
// Requires M%64==0, N%64==0, K%16==0 (true for all calls here).
template <bool TRANS_B, bool RESID>
__global__ __launch_bounds__(256) void gemm64(const float* __restrict__ A,
                                              const float* __restrict__ Bm,
                                              float* __restrict__ C,
                                              const float* __restrict__ R,
                                              int M, int Nn, int K,
                                              long sA, long sB, long sC, long sR,
                                              float alpha) {
    constexpr int BM = 64, BN = 64, BK = 16;
    __shared__ float As[BK][BM + 4];
    __shared__ float Bs[BK][BN + 4];
    const int bz = blockIdx.z;
    A += (long)bz * sA;
    Bm += (long)bz * sB;
    C += (long)bz * sC;
    if (RESID) R += (long)bz * sR;
    const int row0 = blockIdx.y * BM, col0 = blockIdx.x * BN;
    const int tid = threadIdx.x;
    const int tx = tid & 15, ty = tid >> 4;
    float acc[4][4] = {};
    for (int k0 = 0; k0 < K; k0 += BK) {
        {   // A tile: As[k][row]
            int r = tid >> 2;
            int kk = (tid & 3) * 4;
            float4 v = *(const float4*)(A + (long)(row0 + r) * K + k0 + kk);
            As[kk + 0][r] = v.x; As[kk + 1][r] = v.y;
            As[kk + 2][r] = v.z; As[kk + 3][r] = v.w;
        }
        if (!TRANS_B) {  // B: KxN row-major -> Bs[k][n]
            int kk = tid >> 4;
            int c = (tid & 15) * 4;
            float4 v = *(const float4*)(Bm + (long)(k0 + kk) * Nn + col0 + c);
            Bs[kk][c + 0] = v.x; Bs[kk][c + 1] = v.y;
            Bs[kk][c + 2] = v.z; Bs[kk][c + 3] = v.w;
        } else {         // B: NxK row-major -> Bs[k][n] = B[n][k]
            int n = tid >> 2;
            int kk = (tid & 3) * 4;
            float4 v = *(const float4*)(Bm + (long)(col0 + n) * K + k0 + kk);
            Bs[kk + 0][n] = v.x; Bs[kk + 1][n] = v.y;
            Bs[kk + 2][n] = v.z; Bs[kk + 3][n] = v.w;
        }
        __syncthreads();
#pragma unroll
        for (int k = 0; k < BK; k++) {
            float a[4], b[4];
#pragma unroll
            for (int i = 0; i < 4; i++) a[i] = As[k][ty * 4 + i];
#pragma unroll
            for (int j = 0; j < 4; j++) b[j] = Bs[k][tx * 4 + j];
#pragma unroll
            for (int i = 0; i < 4; i++)
#pragma unroll
                for (int j = 0; j < 4; j++) acc[i][j] += a[i] * b[j];
        }
        __syncthreads();
    }
#pragma unroll
    for (int i = 0; i < 4; i++) {
        int r = row0 + ty * 4 + i;
#pragma unroll
        for (int j = 0; j < 4; j++) {
            int c = col0 + tx * 4 + j;
            float val = acc[i][j] * alpha;
            if (RESID) val += R[(long)r * Nn + c];
            C[(long)r * Nn + c] = val;
        }
    }
}

// ---------------- row softmax over 512 (one warp per row) -------------------
__global__ __launch_bounds__(256) void softmax_kernel() {
    long row = (long)blockIdx.x * 8 + (threadIdx.x >> 5);
    int lane = threadIdx.x & 31;
    if (row >= (long)B_ * Q_ * N_) return;
    float* p = g_S + row * N_;
    float vals[16];
    float m = -1e30f;
#pragma unroll
    for (int i = 0; i < 16; i++) {
        vals[i] = p[lane + i * 32];
        m = fmaxf(m, vals[i]);
    }
#pragma unroll
    for (int o = 16; o; o >>= 1) m = fmaxf(m, __shfl_xor_sync(0xffffffffu, m, o));
    float s = 0.f;
#pragma unroll
    for (int i = 0; i < 16; i++) {
        vals[i] = __expf(vals[i] - m);
        s += vals[i];
    }
#pragma unroll
    for (int o = 16; o; o >>= 1) s += __shfl_xor_sync(0xffffffffu, s, o);
    float inv = 1.f / s;
#pragma unroll
    for (int i = 0; i < 16; i++) p[lane + i * 32] = vals[i] * inv;
}

// ---------------- launch ----------------------------------------------------
extern "C" void kernel_launch(void* const* d_in, const int* in_sizes, int n_in,
                              void* d_out, int out_size) {
    const float* inputs = (const float*)d_in[0];
    // d_in[1] = targets (unused by reference)
    const float* W_in  = (const float*)d_in[2];
    const float* T_mix = (const float*)d_in[3];
    const float* Wq    = (const float*)d_in[4];
    const float* Wk    = (const float*)d_in[5];
    const float* Wv    = (const float*)d_in[6];
    const float* W_out = (const float*)d_in[7];
    const float* A     = (const float*)d_in[8];
    // q_noise / r_noise: dead w.r.t. outputs (covariance path never feeds mu)

    float* out = (float*)d_out;
    float* mgt = out;                                   // (B,Q,N,F)
    float* kal = out + (long)B_ * Q_ * N_ * F_;         // (B,Q,N,F)

    float *tmp, *h, *qb, *kb, *vb, *S, *Fm;
    cudaGetSymbolAddress((void**)&tmp, g_tmp);
    cudaGetSymbolAddress((void**)&h, g_h);
    cudaGetSymbolAddress((void**)&qb, g_q);
    cudaGetSymbolAddress((void**)&kb, g_k);
    cudaGetSymbolAddress((void**)&vb, g_v);
    cudaGetSymbolAddress((void**)&S, g_S);
    cudaGetSymbolAddress((void**)&Fm, g_Fm);

    const long sND = (long)N_ * D_;   // per-(b,q) stride for h/q/k/v
    const long sNN = (long)N_ * N_;   // per-(b,q) stride for S
    const int nBatch = B_ * Q_;       // 384

    // K1: time-mix (B,P,N,F) -> (B,Q,N,F)
    mix_kernel<<<((long)B_ * N_ * F_ + 255) / 256, 256>>>(inputs, T_mix);
    // Fm = I + DT*A
    fm_kernel<<<(N_ * N_ + 255) / 256, 256>>>(A);

    // K2: h = tmp @ W_in   (M=196608, N=256, K=64)
    gemm64<false, false><<<dim3(D_ / 64, BQN / 64, 1), 256>>>(
        tmp, W_in, h, nullptr, BQN, D_, F_, 0, 0, 0, 0, 1.f);

    // K3: q/k/v = h @ W{q,k,v}   (q pre-scaled by 1/sqrt(D)=1/16)
    gemm64<false, false><<<dim3(D_ / 64, BQN / 64, 1), 256>>>(
        h, Wq, qb, nullptr, BQN, D_, D_, 0, 0, 0, 0, 0.0625f);
    gemm64<false, false><<<dim3(D_ / 64, BQN / 64, 1), 256>>>(
        h, Wk, kb, nullptr, BQN, D_, D_, 0, 0, 0, 0, 1.f);
    gemm64<false, false><<<dim3(D_ / 64, BQN / 64, 1), 256>>>(
        h, Wv, vb, nullptr, BQN, D_, D_, 0, 0, 0, 0, 1.f);

    // K4: S = q @ k^T  batched over (b,q)   (512x512x256, NT)
    gemm64<true, false><<<dim3(N_ / 64, N_ / 64, nBatch), 256>>>(
        qb, kb, S, nullptr, N_, N_, D_, sND, sND, sNN, 0, 1.f);

    // K5: row softmax
    softmax_kernel<<<(BQN + 7) / 8, 256>>>();

    // K6: h = h + S @ v   batched   (512x256x512, NN, residual)
    gemm64<false, true><<<dim3(D_ / 64, N_ / 64, nBatch), 256>>>(
        S, vb, h, h, N_, D_, N_, sNN, sND, sND, sND, 1.f);

    // K7: mgt = h @ W_out   (M=196608, N=64, K=256)
    gemm64<false, false><<<dim3(F_ / 64, BQN / 64, 1), 256>>>(
        h, W_out, mgt, nullptr, BQN, F_, D_, 0, 0, 0, 0, 1.f);

    // Kalman: mus[:,t] = Fm^{t+1} @ inputs[:,-1]  (covariance path is dead code)
    // step t: kal[b,t] = Fm @ prev[b]   (512x64x512 per batch, 32 batches)
    for (int t = 0; t < Q_; t++) {
        const float* prev;
        long sB;
        if (t == 0) {
            prev = inputs + (long)(P_ - 1) * N_ * F_;   // inputs[:, -1]
            sB = (long)P_ * N_ * F_;
        } else {
            prev = kal + (long)(t - 1) * N_ * F_;
            sB = (long)Q_ * N_ * F_;
        }
        gemm64<false, false><<<dim3(1, N_ / 64, B_), 256>>>(
            Fm, prev, kal + (long)t * N_ * F_, nullptr,
            N_, F_, N_, 0, sB, (long)Q_ * N_ * F_, 0, 1.f);
    }
}

// round 2
// speedup vs baseline: 2.9200x; 2.9200x over previous
#include <cuda_runtime.h>
#include <cstdint>

// Problem dims
#define B_ 32
#define P_ 12
#define N_ 512
#define F_ 64
#define D_ 256
#define Q_ 12
#define DT_ 0.1f

static const int BQN = B_ * Q_ * N_;  // 196608

// ---------------- scratch (device globals; no runtime alloc) ----------------
__device__ float g_tmp[(size_t)B_ * Q_ * N_ * F_];   // mixed inputs  (B,Q,N,F)
__device__ float g_h  [(size_t)B_ * Q_ * N_ * D_];   // hidden        (B,Q,N,D)
__device__ float g_q  [(size_t)B_ * Q_ * N_ * D_];
__device__ float g_k  [(size_t)B_ * Q_ * N_ * D_];
__device__ float g_v  [(size_t)B_ * Q_ * N_ * D_];
__device__ float g_S  [(size_t)B_ * Q_ * N_ * N_];   // scores/attn   (B,Q,N,N)

// ---------------- helpers ----------------------------------------------------
__device__ __forceinline__ uint32_t f2tf32(float f) {
    uint32_t u;
    asm("cvt.rna.tf32.f32 %0, %1;" : "=r"(u) : "f"(f));
    return u;
}

__device__ __forceinline__ void mma_tf32(float* c, const uint32_t* a, const uint32_t* b) {
    asm volatile(
        "mma.sync.aligned.m16n8k8.row.col.f32.tf32.tf32.f32 "
        "{%0,%1,%2,%3}, {%4,%5,%6,%7}, {%8,%9}, {%0,%1,%2,%3};"
        : "+f"(c[0]), "+f"(c[1]), "+f"(c[2]), "+f"(c[3])
        : "r"(a[0]), "r"(a[1]), "r"(a[2]), "r"(a[3]),
          "r"(b[0]), "r"(b[1]));
}

// ---------------- K1: tmp[b,q,n,f] = sum_p inputs[b,p,n,f] * T_mix[p,q] -----
__global__ __launch_bounds__(256) void mix_kernel(const float* __restrict__ in,
                                                  const float* __restrict__ T) {
    __shared__ float Ts[P_][Q_];
    int t = threadIdx.x;
    if (t < P_ * Q_) Ts[t / Q_][t % Q_] = T[t];
    __syncthreads();
    long idx = (long)blockIdx.x * blockDim.x + t;          // over B*N*F
    if (idx >= (long)B_ * N_ * F_) return;
    int f = (int)(idx % F_);
    int n = (int)((idx / F_) % N_);
    int b = (int)(idx / ((long)F_ * N_));
    float vals[P_];
    const float* ip = in + ((long)b * P_ * N_ + n) * F_ + f;
#pragma unroll
    for (int p = 0; p < P_; p++) vals[p] = ip[(long)p * N_ * F_];
    float* op = g_tmp + ((long)b * Q_ * N_ + n) * F_ + f;
#pragma unroll
    for (int q = 0; q < Q_; q++) {
        float s = 0.f;
#pragma unroll
        for (int p = 0; p < P_; p++) s += vals[p] * Ts[p][q];
        op[(long)q * N_ * F_] = s;
    }
}

// ---------------- tf32 tensor-core GEMM --------------------------------------
// C = alpha * A * op(B) (+ R).  A: MxK row-major fp32.
// NN: B is KxN row-major.  NT: B is NxK row-major (C = A*B^T).
// Batched via blockIdx.z with strides. Requires M%BM==0, N%BN==0, K%16==0.
// Warp layout: WARPS_M x WARPS_N, warp tile 64x32 (m16n8k8 frags: 4x4).
template <int BM, int BN, int WARPS_M, int WARPS_N, bool TRANS_B, bool RESID>
__global__ __launch_bounds__(WARPS_M* WARPS_N * 32) void gemm_tf32(
    const float* __restrict__ A, const float* __restrict__ Bm,
    float* __restrict__ C, const float* __restrict__ R,
    int M, int Nn, int K, long sA, long sB, long sC, long sR, float alpha) {
    constexpr int BK = 16;
    constexpr int NT = WARPS_M * WARPS_N * 32;
    constexpr int WTM = BM / WARPS_M;        // 64
    constexpr int WTN = BN / WARPS_N;        // 32
    constexpr int FM = WTM / 16;             // 4
    constexpr int FN = WTN / 8;              // 4
    constexpr int LDA_S = BK + 4;            // 20 (conflict-free frag loads)
    constexpr int LDB_S = BN + 8;            // stride mod 32 == 8
    constexpr int NA4 = BM * BK / (4 * NT);
    constexpr int NB4 = BN * BK / (4 * NT);

    __shared__ __align__(16) uint32_t As[BM][LDA_S];   // [m][k]
    __shared__ __align__(16) uint32_t Bs[BK][LDB_S];   // [k][n]

    const int bz = blockIdx.z;
    A += (long)bz * sA;
    Bm += (long)bz * sB;
    C += (long)bz * sC;
    if (RESID) R += (long)bz * sR;

    const int row0 = blockIdx.y * BM, col0 = blockIdx.x * BN;
    const int tid = threadIdx.x;
    const int lane = tid & 31, wid = tid >> 5;
    const int grp = lane >> 2, qid = lane & 3;
    const int wm = wid / WARPS_N, wn = wid % WARPS_N;
    const int m_base = wm * WTM, n_base = wn * WTN;

    float acc[FM][FN][4] = {};
    float4 pa[NA4], pb[NB4];

    // ---- global load (tile starting at k0) into registers ----
    auto g_load = [&](int k0) {
#pragma unroll
        for (int l = 0; l < NA4; l++) {
            int i = tid + l * NT;
            int r = i >> 2, kq = i & 3;                 // BK/4 == 4
            pa[l] = *(const float4*)(A + (long)(row0 + r) * K + k0 + kq * 4);
        }
#pragma unroll
        for (int l = 0; l < NB4; l++) {
            int i = tid + l * NT;
            if (!TRANS_B) {
                int kk = i / (BN / 4), nq = i % (BN / 4);
                pb[l] = *(const float4*)(Bm + (long)(k0 + kk) * Nn + col0 + nq * 4);
            } else {
                int n = i >> 2, kq = i & 3;
                pb[l] = *(const float4*)(Bm + (long)(col0 + n) * K + k0 + kq * 4);
            }
        }
    };
    // ---- register -> shared (with tf32 conversion) ----
    auto s_store = [&]() {
#pragma unroll
        for (int l = 0; l < NA4; l++) {
            int i = tid + l * NT;
            int r = i >> 2, kq = i & 3;
            uint4 u = {f2tf32(pa[l].x), f2tf32(pa[l].y), f2tf32(pa[l].z), f2tf32(pa[l].w)};
            *(uint4*)&As[r][kq * 4] = u;
        }
#pragma unroll
        for (int l = 0; l < NB4; l++) {
            int i = tid + l * NT;
            if (!TRANS_B) {
                int kk = i / (BN / 4), nq = i % (BN / 4);
                uint4 u = {f2tf32(pb[l].x), f2tf32(pb[l].y), f2tf32(pb[l].z), f2tf32(pb[l].w)};
                *(uint4*)&Bs[kk][nq * 4] = u;
            } else {
                int n = i >> 2, kq = i & 3;
                Bs[kq * 4 + 0][n] = f2tf32(pb[l].x);
                Bs[kq * 4 + 1][n] = f2tf32(pb[l].y);
                Bs[kq * 4 + 2][n] = f2tf32(pb[l].z);
                Bs[kq * 4 + 3][n] = f2tf32(pb[l].w);
            }
        }
    };

    g_load(0);
    s_store();
    __syncthreads();

    const int ktiles = K / BK;
    for (int t = 0; t < ktiles; t++) {
        if (t + 1 < ktiles) g_load((t + 1) * BK);   // prefetch next tile
#pragma unroll
        for (int ks = 0; ks < 2; ks++) {
            const int kk = ks * 8;
            uint32_t af[FM][4], bf[FN][2];
#pragma unroll
            for (int i = 0; i < FM; i++) {
                int m = m_base + i * 16 + grp;
                af[i][0] = As[m][kk + qid];
                af[i][1] = As[m + 8][kk + qid];
                af[i][2] = As[m][kk + qid + 4];
                af[i][3] = As[m + 8][kk + qid + 4];
            }
#pragma unroll
            for (int j = 0; j < FN; j++) {
                int n = n_base + j * 8 + grp;
                bf[j][0] = Bs[kk + qid][n];
                bf[j][1] = Bs[kk + qid + 4][n];
            }
#pragma unroll
            for (int i = 0; i < FM; i++)
#pragma unroll
                for (int j = 0; j < FN; j++) mma_tf32(acc[i][j], af[i], bf[j]);
        }
        __syncthreads();
        if (t + 1 < ktiles) {
            s_store();
            __syncthreads();
        }
    }

    // ---- epilogue ----
#pragma unroll
    for (int i = 0; i < FM; i++) {
        int r0 = row0 + m_base + i * 16 + grp;
#pragma unroll
        for (int j = 0; j < FN; j++) {
            int c = col0 + n_base + j * 8 + qid * 2;
            float2 v0 = {acc[i][j][0] * alpha, acc[i][j][1] * alpha};
            float2 v1 = {acc[i][j][2] * alpha, acc[i][j][3] * alpha};
            if (RESID) {
                float2 r0v = *(const float2*)(R + (long)r0 * Nn + c);
                float2 r1v = *(const float2*)(R + (long)(r0 + 8) * Nn + c);
                v0.x += r0v.x; v0.y += r0v.y;
                v1.x += r1v.x; v1.y += r1v.y;
            }
            *(float2*)(C + (long)r0 * Nn + c) = v0;
            *(float2*)(C + (long)(r0 + 8) * Nn + c) = v1;
        }
    }
}

// ---------------- row softmax over 512 (one warp per row) -------------------
__global__ __launch_bounds__(256) void softmax_kernel() {
    long row = (long)blockIdx.x * 8 + (threadIdx.x >> 5);
    int lane = threadIdx.x & 31;
    if (row >= (long)B_ * Q_ * N_) return;
    float* p = g_S + row * N_;
    float vals[16];
    float m = -1e30f;
#pragma unroll
    for (int i = 0; i < 16; i++) {
        vals[i] = p[lane + i * 32];
        m = fmaxf(m, vals[i]);
    }
#pragma unroll
    for (int o = 16; o; o >>= 1) m = fmaxf(m, __shfl_xor_sync(0xffffffffu, m, o));
    float s = 0.f;
#pragma unroll
    for (int i = 0; i < 16; i++) {
        vals[i] = __expf(vals[i] - m);
        s += vals[i];
    }
#pragma unroll
    for (int o = 16; o; o >>= 1) s += __shfl_xor_sync(0xffffffffu, s, o);
    float inv = 1.f / s;
#pragma unroll
    for (int i = 0; i < 16; i++) p[lane + i * 32] = vals[i] * inv;
}

// ---------------- launch ----------------------------------------------------
extern "C" void kernel_launch(void* const* d_in, const int* in_sizes, int n_in,
                              void* d_out, int out_size) {
    const float* inputs = (const float*)d_in[0];
    const float* W_in  = (const float*)d_in[2];
    const float* T_mix = (const float*)d_in[3];
    const float* Wq    = (const float*)d_in[4];
    const float* Wk    = (const float*)d_in[5];
    const float* Wv    = (const float*)d_in[6];
    const float* W_out = (const float*)d_in[7];
    const float* A     = (const float*)d_in[8];
    // q_noise / r_noise: dead w.r.t. outputs (covariance path never feeds mu)

    float* out = (float*)d_out;
    float* mgt = out;                                   // (B,Q,N,F)
    float* kal = out + (long)B_ * Q_ * N_ * F_;         // (B,Q,N,F)

    float *tmp, *h, *qb, *kb, *vb, *S;
    cudaGetSymbolAddress((void**)&tmp, g_tmp);
    cudaGetSymbolAddress((void**)&h, g_h);
    cudaGetSymbolAddress((void**)&qb, g_q);
    cudaGetSymbolAddress((void**)&kb, g_k);
    cudaGetSymbolAddress((void**)&vb, g_v);
    cudaGetSymbolAddress((void**)&S, g_S);

    const long sND = (long)N_ * D_;
    const long sNN = (long)N_ * N_;
    const int nBatch = B_ * Q_;   // 384

    // K1: time-mix (B,P,N,F) -> (B,Q,N,F)
    mix_kernel<<<((long)B_ * N_ * F_ + 255) / 256, 256>>>(inputs, T_mix);

    // K2: h = tmp @ W_in   (M=196608, N=256, K=64)
    gemm_tf32<128, 128, 2, 4, false, false><<<dim3(D_ / 128, BQN / 128, 1), 256>>>(
        tmp, W_in, h, nullptr, BQN, D_, F_, 0, 0, 0, 0, 1.f);

    // K3: q/k/v = h @ W{q,k,v}   (q pre-scaled by 1/sqrt(D)=1/16)
    gemm_tf32<128, 128, 2, 4, false, false><<<dim3(D_ / 128, BQN / 128, 1), 256>>>(
        h, Wq, qb, nullptr, BQN, D_, D_, 0, 0, 0, 0, 0.0625f);
    gemm_tf32<128, 128, 2, 4, false, false><<<dim3(D_ / 128, BQN / 128, 1), 256>>>(
        h, Wk, kb, nullptr, BQN, D_, D_, 0, 0, 0, 0, 1.f);
    gemm_tf32<128, 128, 2, 4, false, false><<<dim3(D_ / 128, BQN / 128, 1), 256>>>(
        h, Wv, vb, nullptr, BQN, D_, D_, 0, 0, 0, 0, 1.f);

    // K4: S = q @ k^T  batched over (b,q)   (512x512x256, NT)
    gemm_tf32<128, 128, 2, 4, true, false><<<dim3(N_ / 128, N_ / 128, nBatch), 256>>>(
        qb, kb, S, nullptr, N_, N_, D_, sND, sND, sNN, 0, 1.f);

    // K5: row softmax
    softmax_kernel<<<(BQN + 7) / 8, 256>>>();

    // K6: h = h + S @ v   batched   (512x256x512, NN, residual)
    gemm_tf32<128, 128, 2, 4, false, true><<<dim3(D_ / 128, N_ / 128, nBatch), 256>>>(
        S, vb, h, h, N_, D_, N_, sNN, sND, sND, sND, 1.f);

    // K7: mgt = h @ W_out   (M=196608, N=64, K=256)
    gemm_tf32<128, 64, 2, 2, false, false><<<dim3(F_ / 64, BQN / 128, 1), 128>>>(
        h, W_out, mgt, nullptr, BQN, F_, D_, 0, 0, 0, 0, 1.f);

    // Kalman (residual form, tf32-safe):
    //   mu_t = mu_{t-1} + DT * (A @ mu_{t-1})
    // The identity part of Fm = I + DT*A is carried exactly in fp32 via the
    // residual add; tf32 error only touches the small DT*A@mu correction.
    for (int t = 0; t < Q_; t++) {
        const float* prev;
        long sB;
        if (t == 0) {
            prev = inputs + (long)(P_ - 1) * N_ * F_;   // inputs[:, -1]
            sB = (long)P_ * N_ * F_;
        } else {
            prev = kal + (long)(t - 1) * N_ * F_;
            sB = (long)Q_ * N_ * F_;
        }
        gemm_tf32<128, 64, 2, 2, false, true><<<dim3(1, N_ / 128, B_), 128>>>(
            A, prev, kal + (long)t * N_ * F_, prev,
            N_, F_, N_, 0, sB, (long)Q_ * N_ * F_, sB, DT_);
    }
}